// round 9
// baseline (speedup 1.0000x reference)
#include <cuda_runtime.h>
#include <cstdint>

// PointPillarsBEV R8 (resubmit — R8 bench was an infra failure; design untested).
// Learned R4/R6/R7: expand (gathers) and pfn are both issue/L1-bound -> mixing them
// never overlaps, and expand's guarded scattered gathers are a wavefront storm.
// New pipeline (3 launches):
//   prep:   per-pillar zero acc cell + owner-election CAS (dedup).
//   stage:  pfn-ALL-batches (R6-optimal warp/pillar) striped with flag-skipping
//           dense ZERO of out (pure STG stream, no gathers).
//   inject: owner warp copies its cell's 64 summed channels acc->out (contiguous
//           256B read, plain scattered stores, no atomics), then resets owner.

#define BEV_W 512
#define NPILLARS 12000
#define NPTS 32
#define DIN 10
#define CCH 64
#define HW 262144                    // 512*512
#define NBATCH 4
#define PPB 8                        // pillars per 256-thread pfn block
#define NPFN_TOT (NBATCH * NPILLARS / PPB)   // 6000
#define NZCHUNK 16384                // zero chunks (256 thr, 4 float4 each) = 268MB
#define STAGE_GRID 24576             // pfn at bid&3==3 (6144 slots), zero elsewhere

__device__ float g_acc[(size_t)NBATCH * HW * CCH];   // touched cells only
__device__ int   g_owner[NBATCH * HW];               // pidx+1 of owner, 0=untouched

__device__ __forceinline__ uint64_t pack2(float lo, float hi) {
    uint64_t r; asm("mov.b64 %0, {%1, %2};" : "=l"(r) : "f"(lo), "f"(hi)); return r;
}
__device__ __forceinline__ void unpack2(uint64_t v, float& lo, float& hi) {
    asm("mov.b64 {%0, %1}, %2;" : "=f"(lo), "=f"(hi) : "l"(v));
}
__device__ __forceinline__ uint64_t fma2(uint64_t a, uint64_t b, uint64_t c) {
    uint64_t d; asm("fma.rn.f32x2 %0, %1, %2, %3;" : "=l"(d) : "l"(a), "l"(b), "l"(c)); return d;
}

// ---------------- prep: warp per pillar -> zero acc cell + claim ownership ----------------
__global__ __launch_bounds__(256) void prep_kernel(const int* __restrict__ coords) {
    const int warp = threadIdx.x >> 5, lane = threadIdx.x & 31;
    const int pidx = blockIdx.x * PPB + warp;            // [0, 48000)
    const int b = pidx / NPILLARS;
    const int y = __ldg(&coords[(size_t)pidx * 2 + 0]);
    const int x = __ldg(&coords[(size_t)pidx * 2 + 1]);
    const int cell = b * HW + y * BEV_W + x;
    ((float2*)(g_acc + (size_t)cell * CCH))[lane] = make_float2(0.f, 0.f);
    if (lane == 0) atomicCAS(&g_owner[cell], 0, pidx + 1);
}

// ---------------- PFN: 1 warp per pillar, lane = channels (c, c+32) ----------------
__device__ __forceinline__ void do_pfn(
    const float* __restrict__ pillars, const int* __restrict__ coords,
    const float* __restrict__ w, const float* __restrict__ bias, int pfnBlk)
{
    const int warp = threadIdx.x >> 5, lane = threadIdx.x & 31;
    const int pidx = pfnBlk * PPB + warp;                // flat pillar [0, 48000)

    __shared__ __align__(16) float s_pts[PPB][DIN][NPTS];   // dim-major

    // lane = point: 5 x LDG.64
    const float2* src2 = (const float2*)(pillars + ((size_t)pidx * NPTS + lane) * DIN);
    float v[DIN];
    #pragma unroll
    for (int i = 0; i < 5; i++) { float2 t = src2[i]; v[2*i] = t.x; v[2*i+1] = t.y; }
    #pragma unroll
    for (int d = 0; d < DIN; d++) s_pts[warp][d][lane] = v[d];

    uint64_t wA[DIN], wB[DIN];                           // dup-packed weights
    #pragma unroll
    for (int d = 0; d < DIN; d++) {
        float wa = w[d * CCH + lane], wb = w[d * CCH + lane + 32];
        wA[d] = pack2(wa, wa); wB[d] = pack2(wb, wb);
    }
    const float ba = bias[lane], bb = bias[lane + 32];
    const uint64_t biasA = pack2(ba, ba), biasB = pack2(bb, bb);

    __syncwarp();

    float mA = 0.f, mB = 0.f;                            // relu >= 0 -> 0-init exact
    #pragma unroll
    for (int k = 0; k < NPTS / 4; k++) {                 // 4 points per iter
        uint64_t sA0 = biasA, sA1 = biasA, sB0 = biasB, sB1 = biasB;
        #pragma unroll
        for (int d = 0; d < DIN; d++) {
            // LDS.128 broadcast: points (4k..4k+3) at dim d, directly fma2-ready
            const ulonglong2 X = *reinterpret_cast<const ulonglong2*>(&s_pts[warp][d][4 * k]);
            sA0 = fma2(X.x, wA[d], sA0); sA1 = fma2(X.y, wA[d], sA1);
            sB0 = fma2(X.x, wB[d], sB0); sB1 = fma2(X.y, wB[d], sB1);
        }
        float lo, hi;
        unpack2(sA0, lo, hi); mA = fmaxf(mA, fmaxf(lo, hi));
        unpack2(sA1, lo, hi); mA = fmaxf(mA, fmaxf(lo, hi));
        unpack2(sB0, lo, hi); mB = fmaxf(mB, fmaxf(lo, hi));
        unpack2(sB1, lo, hi); mB = fmaxf(mB, fmaxf(lo, hi));
    }

    const int b = pidx / NPILLARS;
    const int y = __ldg(&coords[(size_t)pidx * 2 + 0]);
    const int x = __ldg(&coords[(size_t)pidx * 2 + 1]);
    const int cell = b * HW + y * BEV_W + x;
    float* a = g_acc + (size_t)cell * CCH;
    atomicAdd(a + lane, mA);                             // 256B contiguous burst
    atomicAdd(a + lane + 32, mB);
}

// ---------------- dense zero of out, skipping owned cells (inject covers them) ----------------
__device__ __forceinline__ void do_zero(float* __restrict__ out, int zid) {
    const int T = zid * 256 + threadIdx.x;               // [0, 4,194,304)
    const int eb = T >> 20;                              // batch
    const int t = T & 1048575;
    const int g = t & 65535;                             // cell-group (4 cells)
    const int cb = t >> 16;                              // channel base 0..15
    const int cell4 = g << 2;

    const int4 f = *(const int4*)(g_owner + eb * HW + cell4);
    float* obase = out + (size_t)eb * CCH * HW;
    const bool clean = (f.x | f.y | f.z | f.w) == 0;

    #pragma unroll
    for (int k = 0; k < 4; k++) {
        const int c = cb + 16 * k;
        float* d4 = obase + (size_t)c * HW + cell4;
        if (clean) {
            *(float4*)d4 = make_float4(0.f, 0.f, 0.f, 0.f);
        } else {                                          // ~18% of groups: masked stores
            if (!f.x) d4[0] = 0.f;
            if (!f.y) d4[1] = 0.f;
            if (!f.z) d4[2] = 0.f;
            if (!f.w) d4[3] = 0.f;
        }
    }
}

__global__ __launch_bounds__(256) void stage_kernel(
    const float* __restrict__ pillars, const int* __restrict__ coords,
    const float* __restrict__ w, const float* __restrict__ bias,
    float* __restrict__ out)
{
    const int bid = blockIdx.x;
    if ((bid & 3) == 3) {
        const int pfnBlk = bid >> 2;                     // [0, 6144)
        if (pfnBlk < NPFN_TOT) do_pfn(pillars, coords, w, bias, pfnBlk);
    } else {
        const int zid = bid - ((bid + 1) >> 2);          // contiguous over non-pfn bids
        if (zid < NZCHUNK) do_zero(out, zid);
    }
}

// ---------------- inject: owner warp copies acc cell -> out, resets owner ----------------
__global__ __launch_bounds__(256) void inject_kernel(
    const int* __restrict__ coords, float* __restrict__ out)
{
    const int warp = threadIdx.x >> 5, lane = threadIdx.x & 31;
    const int pidx = blockIdx.x * PPB + warp;            // [0, 48000)
    const int b = pidx / NPILLARS;
    const int y = __ldg(&coords[(size_t)pidx * 2 + 0]);
    const int x = __ldg(&coords[(size_t)pidx * 2 + 1]);
    const int cell = b * HW + y * BEV_W + x;

    if (g_owner[cell] == pidx + 1) {                     // owner does the (deduped) write
        const float2 v = ((const float2*)(g_acc + (size_t)cell * CCH))[lane];
        const size_t o = ((size_t)(b * CCH + 2 * lane) << 18) + (y * BEV_W + x);
        out[o] = v.x;                                    // plain stores: zero-pass skipped
        out[o + HW] = v.y;                               //   these cells entirely
        __syncwarp();
        if (lane == 0) g_owner[cell] = 0;                // clean state for next call
    }
}

extern "C" void kernel_launch(void* const* d_in, const int* in_sizes, int n_in,
                              void* d_out, int out_size) {
    const float* pillars = (const float*)d_in[0];
    const int*   coords  = (const int*)d_in[1];
    const float* pfn_w   = (const float*)d_in[2];
    const float* pfn_b   = (const float*)d_in[3];
    float* out = (float*)d_out;

    prep_kernel<<<NBATCH * NPILLARS / PPB, 256>>>(coords);               // 6000
    stage_kernel<<<STAGE_GRID, 256>>>(pillars, coords, pfn_w, pfn_b, out);
    inject_kernel<<<NBATCH * NPILLARS / PPB, 256>>>(coords, out);        // 6000
}

// round 10
// speedup vs baseline: 2.1021x; 2.1021x over previous
#include <cuda_runtime.h>
#include <cstdint>

// PointPillarsBEV R10 — two serial kernels, no prep, self-cleaning state.
//  pfn_all: warp/pillar PFN -> flag[cell]=1, contiguous atomicAdd into cell-major
//           g_acc (64 consecutive floats -> 4 L2 sectors/warp: atomics ~1us total).
//  expand:  block = 256 consecutive cells x 64 ch. Flags staged in shared; 83% of
//           float4 stores are pure zeros; sparse groups gather acc with L1 reuse
//           (each 256B acc row read once, consumed over 16 c-iters). Block then
//           zeroes its touched acc rows + resets flags -> acc/flag are all-zero at
//           every call start (first call: static zero-init). Deterministic.

#define BEV_W 512
#define NPILLARS 12000
#define NPTS 32
#define DIN 10
#define CCH 64
#define HW 262144                    // 512*512
#define NBATCH 4
#define PPB 8                        // pillars per 256-thread pfn block
#define NPFN_BLKS (NBATCH * NPILLARS / PPB)   // 6000
#define NEXP_BLKS (NBATCH * HW / 256)         // 4096

__device__ float g_acc[(size_t)NBATCH * HW * CCH];   // 268MB, all-zero between calls
__device__ int   g_flag[NBATCH * HW];                // 4MB,  all-zero between calls

__device__ __forceinline__ uint64_t pack2(float lo, float hi) {
    uint64_t r; asm("mov.b64 %0, {%1, %2};" : "=l"(r) : "f"(lo), "f"(hi)); return r;
}
__device__ __forceinline__ void unpack2(uint64_t v, float& lo, float& hi) {
    asm("mov.b64 {%0, %1}, %2;" : "=f"(lo), "=f"(hi) : "l"(v));
}
__device__ __forceinline__ uint64_t fma2(uint64_t a, uint64_t b, uint64_t c) {
    uint64_t d; asm("fma.rn.f32x2 %0, %1, %2, %3;" : "=l"(d) : "l"(a), "l"(b), "l"(c)); return d;
}

// ---------------- PFN all batches: 1 warp per pillar, lane = channels (c, c+32) ----------------
__global__ __launch_bounds__(256) void pfn_kernel(
    const float* __restrict__ pillars,    // (B, P, 32, 10)
    const int*   __restrict__ coords,     // (B, P, 2)
    const float* __restrict__ w,          // (10, 64)
    const float* __restrict__ bias)       // (64,)
{
    const int warp = threadIdx.x >> 5, lane = threadIdx.x & 31;
    const int pidx = blockIdx.x * PPB + warp;            // flat pillar [0, 48000)

    __shared__ __align__(16) float s_pts[PPB][DIN][NPTS];   // dim-major

    // lane = point: 5 x LDG.64 (40B point, 8B aligned)
    const float2* src2 = (const float2*)(pillars + ((size_t)pidx * NPTS + lane) * DIN);
    float v[DIN];
    #pragma unroll
    for (int i = 0; i < 5; i++) { float2 t = src2[i]; v[2*i] = t.x; v[2*i+1] = t.y; }
    #pragma unroll
    for (int d = 0; d < DIN; d++) s_pts[warp][d][lane] = v[d];

    uint64_t wA[DIN], wB[DIN];                           // dup-packed weights
    #pragma unroll
    for (int d = 0; d < DIN; d++) {
        float wa = w[d * CCH + lane], wb = w[d * CCH + lane + 32];
        wA[d] = pack2(wa, wa); wB[d] = pack2(wb, wb);
    }
    const float ba = bias[lane], bb = bias[lane + 32];
    const uint64_t biasA = pack2(ba, ba), biasB = pack2(bb, bb);

    __syncwarp();

    float mA = 0.f, mB = 0.f;                            // relu >= 0 -> 0-init exact
    #pragma unroll
    for (int k = 0; k < NPTS / 4; k++) {                 // 4 points per iter
        uint64_t sA0 = biasA, sA1 = biasA, sB0 = biasB, sB1 = biasB;
        #pragma unroll
        for (int d = 0; d < DIN; d++) {
            // LDS.128 broadcast: points (4k..4k+3) at dim d, fma2-ready u64 pairs
            const ulonglong2 X = *reinterpret_cast<const ulonglong2*>(&s_pts[warp][d][4 * k]);
            sA0 = fma2(X.x, wA[d], sA0); sA1 = fma2(X.y, wA[d], sA1);
            sB0 = fma2(X.x, wB[d], sB0); sB1 = fma2(X.y, wB[d], sB1);
        }
        float lo, hi;
        unpack2(sA0, lo, hi); mA = fmaxf(mA, fmaxf(lo, hi));
        unpack2(sA1, lo, hi); mA = fmaxf(mA, fmaxf(lo, hi));
        unpack2(sB0, lo, hi); mB = fmaxf(mB, fmaxf(lo, hi));
        unpack2(sB1, lo, hi); mB = fmaxf(mB, fmaxf(lo, hi));
    }

    const int b = pidx / NPILLARS;
    const int y = __ldg(&coords[(size_t)pidx * 2 + 0]);
    const int x = __ldg(&coords[(size_t)pidx * 2 + 1]);
    const int cell = b * HW + y * BEV_W + x;
    if (lane == 0) g_flag[cell] = 1;
    float* a = g_acc + (size_t)cell * CCH;
    atomicAdd(a + lane, mA);                             // 128B contiguous: 4 sectors/warp
    atomicAdd(a + lane + 32, mB);
}

// ---------------- expand: block = 256 consecutive cells x 64 channels ----------------
__global__ __launch_bounds__(256) void expand_kernel(float* __restrict__ out) {
    const int bid = blockIdx.x;
    const int b  = bid >> 10;                            // batch
    const int c0 = (bid & 1023) << 8;                    // first cell of this block

    __shared__ int sflag[256];
    const int t = threadIdx.x;
    if (t < 64)
        ((int4*)sflag)[t] = ((const int4*)(g_flag + b * HW + c0))[t];
    __syncthreads();

    const int g = t >> 2;                                // cell-group 0..63 (4 cells)
    const int ci = t & 3;                                // channel quarter
    const int cell0 = c0 + (g << 2);

    const int f0 = sflag[(g << 2) + 0], f1 = sflag[(g << 2) + 1];
    const int f2 = sflag[(g << 2) + 2], f3 = sflag[(g << 2) + 3];
    const bool any = (f0 | f1 | f2 | f3) != 0;

    const float* arow = g_acc + ((size_t)b * HW + cell0) * CCH;
    float* obase = out + (size_t)b * CCH * HW + cell0;

    #pragma unroll
    for (int k = 0; k < 16; k++) {
        const int c = (ci << 4) + k;                     // thread's 16 channels
        float4 val = make_float4(0.f, 0.f, 0.f, 0.f);
        if (any) {                                       // ~17% of groups
            if (f0) val.x = arow[c];                     // rows L1-resident across k
            if (f1) val.y = arow[CCH + c];
            if (f2) val.z = arow[2 * CCH + c];
            if (f3) val.w = arow[3 * CCH + c];
        }
        *(float4*)(obase + (size_t)c * HW) = val;        // coalesced dense store
    }

    // cleanup: this block exclusively owns cells [c0, c0+256) -> zero acc + flags
    __syncthreads();                                     // all acc reads done
    if (sflag[t]) {
        float4* ar = (float4*)(g_acc + ((size_t)b * HW + c0 + t) * CCH);
        #pragma unroll
        for (int k = 0; k < 16; k++) ar[k] = make_float4(0.f, 0.f, 0.f, 0.f);
    }
    g_flag[b * HW + c0 + t] = 0;
}

extern "C" void kernel_launch(void* const* d_in, const int* in_sizes, int n_in,
                              void* d_out, int out_size) {
    const float* pillars = (const float*)d_in[0];
    const int*   coords  = (const int*)d_in[1];
    const float* pfn_w   = (const float*)d_in[2];
    const float* pfn_b   = (const float*)d_in[3];
    float* out = (float*)d_out;

    pfn_kernel<<<NPFN_BLKS, 256>>>(pillars, coords, pfn_w, pfn_b);
    expand_kernel<<<NEXP_BLKS, 256>>>(out);
}

// round 13
// speedup vs baseline: 2.2649x; 1.0775x over previous
#include <cuda_runtime.h>
#include <cuda_bf16.h>
#include <cstdint>

// PointPillarsBEV R13 — R12 resubmit (infra failed) + bugfix: B operand uses plain
// ldmatrix (NOT .trans): B staged [n][k] with k contiguous is already the col-major
// fragment layout for m16n8k16 (lane holds 2 consecutive k at fixed n).
// PFN on mma.sync HMMA (sm_100 base target; tcgen05 unsupported by harness ptxas).
// Math: D[c,n] = sum_d W[d,c]*X[n,d], K=32 packed bf16 hi/lo:
//   k=3d:(wh,xh)  k=3d+1:(wh,xl)  k=3d+2:(wl,xh)  k=30,31:0   (err ~2^-16)
// Epilogue: fragment column-max via 2x shfl.xor, +bias, relu, 2 contiguous
// atomicAdds into cell-major g_acc. Expand = R10 (57.7us, near store floor).

#define BEV_W 512
#define NPILLARS 12000
#define NPTS 32
#define DIN 10
#define CCH 64
#define HW 262144
#define NBATCH 4

#define WPB 4                        // warps per block (1 pillar each per iter)
#define ITERS 10
#define PFN_BLOCKS 1200              // 1200*4*10 = 48000 pillars
#define NEXP_BLKS 4096

#define ASTRIDE 80                   // bytes per 32-bf16 row (padded)

__device__ float g_acc[(size_t)NBATCH * HW * CCH];   // all-zero between calls
__device__ int   g_flag[NBATCH * HW];                // all-zero between calls

__device__ __forceinline__ uint32_t smem_u32(const void* p) {
    uint32_t a; asm("{ .reg .u64 t; cvta.to.shared.u64 t, %1; cvt.u32.u64 %0, t; }" : "=r"(a) : "l"(p));
    return a;
}
__device__ __forceinline__ void ldsm_x4(uint32_t& r0, uint32_t& r1, uint32_t& r2,
                                        uint32_t& r3, uint32_t addr) {
    asm volatile("ldmatrix.sync.aligned.m8n8.x4.shared.b16 {%0,%1,%2,%3}, [%4];"
                 : "=r"(r0), "=r"(r1), "=r"(r2), "=r"(r3) : "r"(addr));
}
__device__ __forceinline__ void mma_bf16(float& d0, float& d1, float& d2, float& d3,
                                         const uint32_t* a, uint32_t b0, uint32_t b1) {
    asm volatile(
        "mma.sync.aligned.m16n8k16.row.col.f32.bf16.bf16.f32 "
        "{%0,%1,%2,%3}, {%4,%5,%6,%7}, {%8,%9}, {%0,%1,%2,%3};"
        : "+f"(d0), "+f"(d1), "+f"(d2), "+f"(d3)
        : "r"(a[0]), "r"(a[1]), "r"(a[2]), "r"(a[3]), "r"(b0), "r"(b1));
}
__device__ __forceinline__ unsigned short bfbits(float v) {
    __nv_bfloat16 h = __float2bfloat16(v);
    unsigned short s; *((__nv_bfloat16*)&s) = h; return s;
}

// ---------------- PFN via mma.sync ----------------
__global__ __launch_bounds__(128) void pfn_mma_kernel(
    const float* __restrict__ pillars,    // (B,P,32,10)
    const int*   __restrict__ coords,     // (B,P,2)
    const float* __restrict__ w,          // (10,64)
    const float* __restrict__ bias)       // (64,)
{
    __shared__ __align__(16) unsigned char sA[64 * ASTRIDE];
    __shared__ __align__(16) unsigned char sB[WPB][32 * ASTRIDE];

    const int tid = threadIdx.x, wid = tid >> 5, lane = tid & 31;

    // ---- build A (64 x 32 bf16), rows = channels ----
    if (tid < 64) {
        const int c = tid;
        unsigned short v[32];
        #pragma unroll
        for (int d = 0; d < DIN; d++) {
            float wv = w[d * CCH + c];
            unsigned short hb = bfbits(wv);
            float hf = __bfloat162float(*((__nv_bfloat16*)&hb));
            unsigned short lb = bfbits(wv - hf);
            v[3*d] = hb; v[3*d+1] = hb; v[3*d+2] = lb;
        }
        v[30] = 0; v[31] = 0;
        uint32_t u[16];
        #pragma unroll
        for (int j = 0; j < 16; j++) u[j] = (uint32_t)v[2*j] | ((uint32_t)v[2*j+1] << 16);
        #pragma unroll
        for (int q4 = 0; q4 < 4; q4++)
            *(uint4*)(sA + c * ASTRIDE + q4 * 16) =
                make_uint4(u[4*q4], u[4*q4+1], u[4*q4+2], u[4*q4+3]);
    }
    __syncthreads();

    // ---- load A fragments: [mt][ks] (m16 tile mt, k16 chunk ks) ----
    uint32_t afr[4][2][4];
    {
        const int row = lane & 15;                 // lanes 0-15: rows; 16-31: +16B col
        const int col16 = (lane >= 16) ? 16 : 0;
        const uint32_t abase = smem_u32(sA);
        #pragma unroll
        for (int mt = 0; mt < 4; mt++)
            #pragma unroll
            for (int ks = 0; ks < 2; ks++)
                ldsm_x4(afr[mt][ks][0], afr[mt][ks][1], afr[mt][ks][2], afr[mt][ks][3],
                        abase + (16 * mt + row) * ASTRIDE + 32 * ks + col16);
    }

    const int q = lane & 3, g = lane >> 2;
    const float bv0 = bias[16 * q + g];
    const float bv1 = bias[16 * q + g + 8];
    // B ldmatrix addresses: matrix j <- lanes 8j..8j+7: row n=lane&7, bytes (lane>>3)*16
    const uint32_t baddr_lane = smem_u32(sB[wid]) + (lane & 7) * ASTRIDE + (lane >> 3) * 16;

    const int p0 = blockIdx.x * (WPB * ITERS);

    // prefetch iter 0 points (lane = point, coalesced 5x LDG.64)
    float xc[DIN];
    {
        const float2* src = (const float2*)(pillars +
            ((size_t)(p0 + wid) * NPTS + lane) * DIN);
        #pragma unroll
        for (int i = 0; i < 5; i++) { float2 t = src[i]; xc[2*i] = t.x; xc[2*i+1] = t.y; }
    }

    for (int it = 0; it < ITERS; it++) {
        const int pidx = p0 + it * WPB + wid;

        // ---- convert current points, store B row [n][k] ----
        {
            unsigned short v[32];
            #pragma unroll
            for (int d = 0; d < DIN; d++) {
                unsigned short hb = bfbits(xc[d]);
                float hf = __bfloat162float(*((__nv_bfloat16*)&hb));
                unsigned short lb = bfbits(xc[d] - hf);
                v[3*d] = hb; v[3*d+1] = lb; v[3*d+2] = hb;
            }
            v[30] = 0; v[31] = 0;
            uint32_t u[16];
            #pragma unroll
            for (int j = 0; j < 16; j++) u[j] = (uint32_t)v[2*j] | ((uint32_t)v[2*j+1] << 16);
            #pragma unroll
            for (int q4 = 0; q4 < 4; q4++)
                *(uint4*)(sB[wid] + lane * ASTRIDE + q4 * 16) =
                    make_uint4(u[4*q4], u[4*q4+1], u[4*q4+2], u[4*q4+3]);
        }

        // ---- prefetch next iter's points (hides LDG under mma) ----
        if (it + 1 < ITERS) {
            const float2* src = (const float2*)(pillars +
                ((size_t)(pidx + WPB) * NPTS + lane) * DIN);
            #pragma unroll
            for (int i = 0; i < 5; i++) { float2 t = src[i]; xc[2*i] = t.x; xc[2*i+1] = t.y; }
        }

        __syncwarp();

        // ---- GEMM + in-fragment max over points ----
        float M[4][2];
        #pragma unroll
        for (int mt = 0; mt < 4; mt++) { M[mt][0] = -3.0e38f; M[mt][1] = -3.0e38f; }

        #pragma unroll
        for (int nt = 0; nt < 4; nt++) {       // 8 points per n-tile
            uint32_t b0, b1, b2, b3;           // {b0,b1}=K0-15, {b2,b3}=K16-31 (no trans!)
            ldsm_x4(b0, b1, b2, b3, baddr_lane + nt * 8 * ASTRIDE);
            #pragma unroll
            for (int mt = 0; mt < 4; mt++) {
                float d0 = 0.f, d1 = 0.f, d2 = 0.f, d3 = 0.f;
                mma_bf16(d0, d1, d2, d3, afr[mt][0], b0, b1);
                mma_bf16(d0, d1, d2, d3, afr[mt][1], b2, b3);
                float m0 = fmaxf(d0, d1);      // row 16mt+g: 2 points
                float m1 = fmaxf(d2, d3);      // row 16mt+g+8
                m0 = fmaxf(m0, __shfl_xor_sync(0xffffffffu, m0, 1));
                m0 = fmaxf(m0, __shfl_xor_sync(0xffffffffu, m0, 2));
                m1 = fmaxf(m1, __shfl_xor_sync(0xffffffffu, m1, 1));
                m1 = fmaxf(m1, __shfl_xor_sync(0xffffffffu, m1, 2));
                M[mt][0] = fmaxf(M[mt][0], m0);
                M[mt][1] = fmaxf(M[mt][1], m1);
            }
        }

        // ---- epilogue: lane (q,g) -> channels 16q+g, 16q+g+8 (quad-uniform M) ----
        float va = (q == 0) ? M[0][0] : (q == 1) ? M[1][0] : (q == 2) ? M[2][0] : M[3][0];
        float vb = (q == 0) ? M[0][1] : (q == 1) ? M[1][1] : (q == 2) ? M[2][1] : M[3][1];
        va = fmaxf(va + bv0, 0.f);             // max_n relu(s+b) = relu(max_n s + b)
        vb = fmaxf(vb + bv1, 0.f);

        const int b = pidx / NPILLARS;
        const int yy = __ldg(&coords[(size_t)pidx * 2 + 0]);
        const int xx = __ldg(&coords[(size_t)pidx * 2 + 1]);
        const int cell = b * HW + yy * BEV_W + xx;
        if (lane == 0) g_flag[cell] = 1;
        float* a = g_acc + (size_t)cell * CCH;
        atomicAdd(a + 16 * q + g, va);         // 64 ch within one 256B region
        atomicAdd(a + 16 * q + g + 8, vb);
        __syncwarp();                           // B buffer reusable next iter
    }
}

// ---------------- expand (unchanged from R10) ----------------
__global__ __launch_bounds__(256) void expand_kernel(float* __restrict__ out) {
    const int bid = blockIdx.x;
    const int b  = bid >> 10;
    const int c0 = (bid & 1023) << 8;

    __shared__ int sflag[256];
    const int t = threadIdx.x;
    if (t < 64)
        ((int4*)sflag)[t] = ((const int4*)(g_flag + b * HW + c0))[t];
    __syncthreads();

    const int g = t >> 2;
    const int ci = t & 3;
    const int cell0 = c0 + (g << 2);

    const int f0 = sflag[(g << 2) + 0], f1 = sflag[(g << 2) + 1];
    const int f2 = sflag[(g << 2) + 2], f3 = sflag[(g << 2) + 3];
    const bool any = (f0 | f1 | f2 | f3) != 0;

    const float* arow = g_acc + ((size_t)b * HW + cell0) * CCH;
    float* obase = out + (size_t)b * CCH * HW + cell0;

    #pragma unroll
    for (int k = 0; k < 16; k++) {
        const int c = (ci << 4) + k;
        float4 val = make_float4(0.f, 0.f, 0.f, 0.f);
        if (any) {
            if (f0) val.x = arow[c];
            if (f1) val.y = arow[CCH + c];
            if (f2) val.z = arow[2 * CCH + c];
            if (f3) val.w = arow[3 * CCH + c];
        }
        *(float4*)(obase + (size_t)c * HW) = val;
    }

    __syncthreads();
    if (sflag[t]) {
        float4* ar = (float4*)(g_acc + ((size_t)b * HW + c0 + t) * CCH);
        #pragma unroll
        for (int k = 0; k < 16; k++) ar[k] = make_float4(0.f, 0.f, 0.f, 0.f);
    }
    g_flag[b * HW + c0 + t] = 0;
}

extern "C" void kernel_launch(void* const* d_in, const int* in_sizes, int n_in,
                              void* d_out, int out_size) {
    const float* pillars = (const float*)d_in[0];
    const int*   coords  = (const int*)d_in[1];
    const float* pfn_w   = (const float*)d_in[2];
    const float* pfn_b   = (const float*)d_in[3];
    float* out = (float*)d_out;

    pfn_mma_kernel<<<PFN_BLOCKS, 128>>>(pillars, coords, pfn_w, pfn_b);
    expand_kernel<<<NEXP_BLKS, 256>>>(out);
}

// round 14
// speedup vs baseline: 2.6962x; 1.1904x over previous
#include <cuda_runtime.h>
#include <cuda_bf16.h>
#include <cstdint>

// PointPillarsBEV R14 — R13 + epilogue/convert surgery.
//  R13 post-mortem: pfn ~44us because the shfl-max reduction ran INSIDE the
//  (nt,mt) loop (64 SHFL + ~190 fmax/pillar, dependent 26-cyc chains x16).
//  R14: (1) accumulate lane-local maxes across nt, shuffle-reduce ONCE at end;
//  (2) blocked K packing (k0-9 hh, k10-19 wh*xl, k20-29 wl*xh) so bf16x2 packed
//  cvt feeds stored u32s directly (lo half via <<16 bit identity);
//  (3) expand: __stcs streaming output stores + skip zero flag-rewrites.

#define BEV_W 512
#define NPILLARS 12000
#define NPTS 32
#define DIN 10
#define CCH 64
#define HW 262144
#define NBATCH 4

#define WPB 4                        // warps per block (1 pillar each per iter)
#define ITERS 10
#define PFN_BLOCKS 1200              // 1200*4*10 = 48000; 300 blocks per batch
#define NEXP_BLKS 4096

#define ASTRIDE 80                   // bytes per 32-bf16 row

__device__ float g_acc[(size_t)NBATCH * HW * CCH];   // all-zero between calls
__device__ int   g_flag[NBATCH * HW];                // all-zero between calls

__device__ __forceinline__ uint32_t smem_u32(const void* p) {
    uint32_t a; asm("{ .reg .u64 t; cvta.to.shared.u64 t, %1; cvt.u32.u64 %0, t; }" : "=r"(a) : "l"(p));
    return a;
}
__device__ __forceinline__ void ldsm_x4(uint32_t& r0, uint32_t& r1, uint32_t& r2,
                                        uint32_t& r3, uint32_t addr) {
    asm volatile("ldmatrix.sync.aligned.m8n8.x4.shared.b16 {%0,%1,%2,%3}, [%4];"
                 : "=r"(r0), "=r"(r1), "=r"(r2), "=r"(r3) : "r"(addr));
}
__device__ __forceinline__ void mma_bf16(float& d0, float& d1, float& d2, float& d3,
                                         const uint32_t* a, uint32_t b0, uint32_t b1) {
    asm volatile(
        "mma.sync.aligned.m16n8k16.row.col.f32.bf16.bf16.f32 "
        "{%0,%1,%2,%3}, {%4,%5,%6,%7}, {%8,%9}, {%0,%1,%2,%3};"
        : "+f"(d0), "+f"(d1), "+f"(d2), "+f"(d3)
        : "r"(a[0]), "r"(a[1]), "r"(a[2]), "r"(a[3]), "r"(b0), "r"(b1));
}
// pack bf16(x0) lo | bf16(x1) hi
__device__ __forceinline__ uint32_t bfpack(float x0, float x1) {
    uint32_t r;
    asm("cvt.rn.bf16x2.f32 %0, %2, %1;" : "=r"(r) : "f"(x0), "f"(x1));
    return r;
}

// convert 10 floats -> packed hi pairs uh[5] and lo pairs ul[5]
__device__ __forceinline__ void hilo10(const float* xv, uint32_t* uh, uint32_t* ul) {
    #pragma unroll
    for (int i = 0; i < 5; i++) {
        const float x0 = xv[2*i], x1 = xv[2*i+1];
        const uint32_t h = bfpack(x0, x1);
        uh[i] = h;
        const float hf0 = __uint_as_float(h << 16);          // bf16 -> f32 bit identity
        const float hf1 = __uint_as_float(h & 0xffff0000u);
        ul[i] = bfpack(x0 - hf0, x1 - hf1);
    }
}

// ---------------- PFN via mma.sync ----------------
__global__ __launch_bounds__(128) void pfn_mma_kernel(
    const float* __restrict__ pillars,    // (B,P,32,10)
    const int*   __restrict__ coords,     // (B,P,2)
    const float* __restrict__ w,          // (10,64)
    const float* __restrict__ bias)       // (64,)
{
    __shared__ __align__(16) unsigned char sA[64 * ASTRIDE];
    __shared__ __align__(16) unsigned char sB[WPB][32 * ASTRIDE];

    const int tid = threadIdx.x, wid = tid >> 5, lane = tid & 31;

    // ---- build A (64ch x 32K): k0-9 wh, k10-19 wh, k20-29 wl, k30-31 0 ----
    if (tid < 64) {
        const int c = tid;
        float wv[DIN];
        #pragma unroll
        for (int d = 0; d < DIN; d++) wv[d] = w[d * CCH + c];
        uint32_t uh[5], ul[5];
        hilo10(wv, uh, ul);
        unsigned char* row = sA + c * ASTRIDE;
        *(uint4*)(row +  0) = make_uint4(uh[0], uh[1], uh[2], uh[3]);
        *(uint4*)(row + 16) = make_uint4(uh[4], uh[0], uh[1], uh[2]);
        *(uint4*)(row + 32) = make_uint4(uh[3], uh[4], ul[0], ul[1]);
        *(uint4*)(row + 48) = make_uint4(ul[2], ul[3], ul[4], 0u);
    }
    __syncthreads();

    // ---- A fragments [mt][ks] ----
    uint32_t afr[4][2][4];
    {
        const int row = lane & 15;
        const int col16 = (lane >= 16) ? 16 : 0;
        const uint32_t abase = smem_u32(sA);
        #pragma unroll
        for (int mt = 0; mt < 4; mt++)
            #pragma unroll
            for (int ks = 0; ks < 2; ks++)
                ldsm_x4(afr[mt][ks][0], afr[mt][ks][1], afr[mt][ks][2], afr[mt][ks][3],
                        abase + (16 * mt + row) * ASTRIDE + 32 * ks + col16);
    }

    const int q = lane & 3, g = lane >> 2;
    const float bv0 = bias[16 * q + g];
    const float bv1 = bias[16 * q + g + 8];
    const uint32_t baddr_lane = smem_u32(sB[wid]) + (lane & 7) * ASTRIDE + (lane >> 3) * 16;

    const int batch = blockIdx.x / 300;               // 300 blocks per batch (40 pillars each)
    const int p0 = blockIdx.x * (WPB * ITERS);

    // prefetch iter 0 points
    float xc[DIN];
    {
        const float2* src = (const float2*)(pillars + ((size_t)(p0 + wid) * NPTS + lane) * DIN);
        #pragma unroll
        for (int i = 0; i < 5; i++) { float2 t = src[i]; xc[2*i] = t.x; xc[2*i+1] = t.y; }
    }

    for (int it = 0; it < ITERS; it++) {
        const int pidx = p0 + it * WPB + wid;

        // ---- convert + store B row [n][k]: k0-9 xh, k10-19 xl, k20-29 xh ----
        {
            uint32_t uh[5], ul[5];
            hilo10(xc, uh, ul);
            unsigned char* row = sB[wid] + lane * ASTRIDE;
            *(uint4*)(row +  0) = make_uint4(uh[0], uh[1], uh[2], uh[3]);
            *(uint4*)(row + 16) = make_uint4(uh[4], ul[0], ul[1], ul[2]);
            *(uint4*)(row + 32) = make_uint4(ul[3], ul[4], uh[0], uh[1]);
            *(uint4*)(row + 48) = make_uint4(uh[2], uh[3], uh[4], 0u);
        }

        // ---- prefetch next points (hide LDG under mma) ----
        if (it + 1 < ITERS) {
            const float2* src = (const float2*)(pillars +
                ((size_t)(pidx + WPB) * NPTS + lane) * DIN);
            #pragma unroll
            for (int i = 0; i < 5; i++) { float2 t = src[i]; xc[2*i] = t.x; xc[2*i+1] = t.y; }
        }

        __syncwarp();

        // ---- GEMM; lane-local max accumulation only (no shfl in loop) ----
        float M[4][2];
        #pragma unroll
        for (int mt = 0; mt < 4; mt++) { M[mt][0] = -3.0e38f; M[mt][1] = -3.0e38f; }

        #pragma unroll
        for (int nt = 0; nt < 4; nt++) {
            uint32_t b0, b1, b2, b3;
            ldsm_x4(b0, b1, b2, b3, baddr_lane + nt * 8 * ASTRIDE);
            #pragma unroll
            for (int mt = 0; mt < 4; mt++) {
                float d0 = 0.f, d1 = 0.f, d2 = 0.f, d3 = 0.f;
                mma_bf16(d0, d1, d2, d3, afr[mt][0], b0, b1);
                mma_bf16(d0, d1, d2, d3, afr[mt][1], b2, b3);
                M[mt][0] = fmaxf(M[mt][0], fmaxf(d0, d1));
                M[mt][1] = fmaxf(M[mt][1], fmaxf(d2, d3));
            }
        }

        // ---- single quad shuffle-reduce at the end ----
        #pragma unroll
        for (int mt = 0; mt < 4; mt++) {
            #pragma unroll
            for (int r = 0; r < 2; r++) {
                float m = M[mt][r];
                m = fmaxf(m, __shfl_xor_sync(0xffffffffu, m, 1));
                m = fmaxf(m, __shfl_xor_sync(0xffffffffu, m, 2));
                M[mt][r] = m;
            }
        }

        float va = (q == 0) ? M[0][0] : (q == 1) ? M[1][0] : (q == 2) ? M[2][0] : M[3][0];
        float vb = (q == 0) ? M[0][1] : (q == 1) ? M[1][1] : (q == 2) ? M[2][1] : M[3][1];
        va = fmaxf(va + bv0, 0.f);
        vb = fmaxf(vb + bv1, 0.f);

        const int yy = __ldg(&coords[(size_t)pidx * 2 + 0]);
        const int xx = __ldg(&coords[(size_t)pidx * 2 + 1]);
        const int cell = batch * HW + yy * BEV_W + xx;
        if (lane == 0) g_flag[cell] = 1;
        float* a = g_acc + (size_t)cell * CCH;
        atomicAdd(a + 16 * q + g, va);
        atomicAdd(a + 16 * q + g + 8, vb);
        __syncwarp();
    }
}

// ---------------- expand: streaming stores, near write floor ----------------
__global__ __launch_bounds__(256) void expand_kernel(float* __restrict__ out) {
    const int bid = blockIdx.x;
    const int b  = bid >> 10;
    const int c0 = (bid & 1023) << 8;

    __shared__ int sflag[256];
    const int t = threadIdx.x;
    if (t < 64)
        ((int4*)sflag)[t] = ((const int4*)(g_flag + b * HW + c0))[t];
    __syncthreads();

    const int g = t >> 2;
    const int ci = t & 3;
    const int cell0 = c0 + (g << 2);

    const int f0 = sflag[(g << 2) + 0], f1 = sflag[(g << 2) + 1];
    const int f2 = sflag[(g << 2) + 2], f3 = sflag[(g << 2) + 3];
    const bool any = (f0 | f1 | f2 | f3) != 0;

    const float* arow = g_acc + ((size_t)b * HW + cell0) * CCH;
    float* obase = out + (size_t)b * CCH * HW + cell0;

    #pragma unroll
    for (int k = 0; k < 16; k++) {
        const int c = (ci << 4) + k;
        float4 val = make_float4(0.f, 0.f, 0.f, 0.f);
        if (any) {
            if (f0) val.x = arow[c];
            if (f1) val.y = arow[CCH + c];
            if (f2) val.z = arow[2 * CCH + c];
            if (f3) val.w = arow[3 * CCH + c];
        }
        __stcs((float4*)(obase + (size_t)c * HW), val);   // streaming: evict-first
    }

    __syncthreads();
    if (sflag[t]) {                                       // cleanup only touched state
        float4* ar = (float4*)(g_acc + ((size_t)b * HW + c0 + t) * CCH);
        #pragma unroll
        for (int k = 0; k < 16; k++) ar[k] = make_float4(0.f, 0.f, 0.f, 0.f);
        g_flag[b * HW + c0 + t] = 0;
    }
}

extern "C" void kernel_launch(void* const* d_in, const int* in_sizes, int n_in,
                              void* d_out, int out_size) {
    const float* pillars = (const float*)d_in[0];
    const int*   coords  = (const int*)d_in[1];
    const float* pfn_w   = (const float*)d_in[2];
    const float* pfn_b   = (const float*)d_in[3];
    float* out = (float*)d_out;

    pfn_mma_kernel<<<PFN_BLOCKS, 128>>>(pillars, coords, pfn_w, pfn_b);
    expand_kernel<<<NEXP_BLKS, 256>>>(out);
}